// round 3
// baseline (speedup 1.0000x reference)
#include <cuda_runtime.h>
#include <cstdint>

// Problem shape constants
// B=16, H=W=32 -> N=1024 spatial, C=1280, d=160, BN = B*N = 16384
#define SZ_B   16
#define SZ_N   1024
#define SZ_C   1280
#define SZ_D   160
#define SZ_BN  (SZ_B * SZ_N)

// ---------------------------------------------------------------------------
// Scratch (static __device__ globals; allocation rules forbid cudaMalloc)
// g_v is reused for cav: v is dead after the pav GEMM, cav produced after.
// Total: ~361 MB
// ---------------------------------------------------------------------------
__device__ float g_k  [(size_t)SZ_B * SZ_N * SZ_D];    //  10.5 MB
__device__ float g_q  [(size_t)SZ_B * SZ_N * SZ_D];    //  10.5 MB
__device__ float g_v  [(size_t)SZ_B * SZ_N * SZ_C];    //  84   MB (reused for cav)
__device__ float g_s  [(size_t)SZ_B * SZ_N * SZ_N];    //  67   MB
__device__ float g_s2 [(size_t)SZ_B * SZ_C * SZ_C];    // 105   MB
__device__ float g_pav[(size_t)SZ_B * SZ_N * SZ_C];    //  84   MB

// ---------------------------------------------------------------------------
// Tiled SGEMM: C[M,N] = A * B, 128x128 tile, KT=8, 256 threads, 8x8 microtile
//   TA=false: A(m,k) = A[m*lda + k]   TA=true: A(m,k) = A[k*lda + m]
//   TB=false: B(k,n) = B[k*ldb + n]   TB=true: B(k,n) = B[n*ldb + k]
// Batched via blockIdx.z with element strides.
// ---------------------------------------------------------------------------
#define GTILE 128
#define GKT   8

template <bool TA, bool TB>
__global__ __launch_bounds__(256, 2)
void sgemm_kernel(const float* __restrict__ A, const float* __restrict__ B,
                  float* __restrict__ C, int M, int N, int K,
                  int lda, int ldb, int ldc,
                  long strideA, long strideB, long strideC)
{
    A += (long)blockIdx.z * strideA;
    B += (long)blockIdx.z * strideB;
    C += (long)blockIdx.z * strideC;

    __shared__ float As[GKT][GTILE];
    __shared__ float Bs[GKT][GTILE];

    const int tid = threadIdx.x;
    const int m0 = blockIdx.y * GTILE;
    const int n0 = blockIdx.x * GTILE;

    const int tx = tid & 15;
    const int ty = tid >> 4;
    const int mw = ty * 8;   // microtile row base within tile
    const int nw = tx * 8;   // microtile col base within tile

    float acc[8][8];
#pragma unroll
    for (int i = 0; i < 8; i++)
#pragma unroll
        for (int j = 0; j < 8; j++) acc[i][j] = 0.f;

    for (int k0 = 0; k0 < K; k0 += GKT) {
        // ------- A tile -> As[kk][mm] -------
        if (!TA) {
            const int mm = tid >> 1;
            const int kk = (tid & 1) * 4;
            const int gm = m0 + mm;
            float4 v = make_float4(0.f, 0.f, 0.f, 0.f);
            if (gm < M)
                v = *reinterpret_cast<const float4*>(A + (long)gm * lda + (k0 + kk));
            As[kk + 0][mm] = v.x; As[kk + 1][mm] = v.y;
            As[kk + 2][mm] = v.z; As[kk + 3][mm] = v.w;
        } else {
            const int kk = tid >> 5;
            const int mm = (tid & 31) * 4;
            const int gm = m0 + mm;
            float4 v = make_float4(0.f, 0.f, 0.f, 0.f);
            if (gm + 3 < M) {
                v = *reinterpret_cast<const float4*>(A + (long)(k0 + kk) * lda + gm);
            } else {
                float t[4];
#pragma unroll
                for (int u = 0; u < 4; u++)
                    t[u] = (gm + u < M) ? A[(long)(k0 + kk) * lda + gm + u] : 0.f;
                v = make_float4(t[0], t[1], t[2], t[3]);
            }
            *reinterpret_cast<float4*>(&As[kk][mm]) = v;
        }
        // ------- B tile -> Bs[kk][nn] -------
        if (!TB) {
            const int kk = tid >> 5;
            const int nn = (tid & 31) * 4;
            const int gn = n0 + nn;
            float4 v = make_float4(0.f, 0.f, 0.f, 0.f);
            if (gn + 3 < N) {
                v = *reinterpret_cast<const float4*>(B + (long)(k0 + kk) * ldb + gn);
            } else {
                float t[4];
#pragma unroll
                for (int u = 0; u < 4; u++)
                    t[u] = (gn + u < N) ? B[(long)(k0 + kk) * ldb + gn + u] : 0.f;
                v = make_float4(t[0], t[1], t[2], t[3]);
            }
            *reinterpret_cast<float4*>(&Bs[kk][nn]) = v;
        } else {
            const int nn = tid >> 1;
            const int kk = (tid & 1) * 4;
            const int gn = n0 + nn;
            float4 v = make_float4(0.f, 0.f, 0.f, 0.f);
            if (gn < N)
                v = *reinterpret_cast<const float4*>(B + (long)gn * ldb + (k0 + kk));
            Bs[kk + 0][nn] = v.x; Bs[kk + 1][nn] = v.y;
            Bs[kk + 2][nn] = v.z; Bs[kk + 3][nn] = v.w;
        }
        __syncthreads();

#pragma unroll
        for (int kk = 0; kk < GKT; kk++) {
            float a[8], b[8];
            *reinterpret_cast<float4*>(&a[0]) = *reinterpret_cast<const float4*>(&As[kk][mw]);
            *reinterpret_cast<float4*>(&a[4]) = *reinterpret_cast<const float4*>(&As[kk][mw + 4]);
            *reinterpret_cast<float4*>(&b[0]) = *reinterpret_cast<const float4*>(&Bs[kk][nw]);
            *reinterpret_cast<float4*>(&b[4]) = *reinterpret_cast<const float4*>(&Bs[kk][nw + 4]);
#pragma unroll
            for (int i = 0; i < 8; i++)
#pragma unroll
                for (int j = 0; j < 8; j++)
                    acc[i][j] = fmaf(a[i], b[j], acc[i][j]);
        }
        __syncthreads();
    }

#pragma unroll
    for (int i = 0; i < 8; i++) {
        const int gm = m0 + mw + i;
        if (gm >= M) continue;
#pragma unroll
        for (int j = 0; j < 8; j += 4) {
            const int gn = n0 + nw + j;
            if (gn + 3 < N) {
                *reinterpret_cast<float4*>(C + (long)gm * ldc + gn) =
                    make_float4(acc[i][j], acc[i][j + 1], acc[i][j + 2], acc[i][j + 3]);
            } else {
#pragma unroll
                for (int u = 0; u < 4; u++)
                    if (gn + u < N) C[(long)gm * ldc + gn + u] = acc[i][j + u];
            }
        }
    }
}

// ---------------------------------------------------------------------------
// In-place row softmax: one block (256 threads) per row of length L
// ---------------------------------------------------------------------------
__global__ void softmax_rows(float* __restrict__ data, int L)
{
    float* p = data + (long)blockIdx.x * L;
    const int tid = threadIdx.x;
    __shared__ float red[8];

    float m = -3.402823466e38f;
    for (int i = tid; i < L; i += 256) m = fmaxf(m, p[i]);
#pragma unroll
    for (int o = 16; o; o >>= 1) m = fmaxf(m, __shfl_xor_sync(0xffffffffu, m, o));
    if ((tid & 31) == 0) red[tid >> 5] = m;
    __syncthreads();
    m = red[0];
#pragma unroll
    for (int w = 1; w < 8; w++) m = fmaxf(m, red[w]);

    float s = 0.f;
    for (int i = tid; i < L; i += 256) {
        float e = __expf(p[i] - m);
        p[i] = e;
        s += e;
    }
#pragma unroll
    for (int o = 16; o; o >>= 1) s += __shfl_xor_sync(0xffffffffu, s, o);
    __syncthreads();  // red[] reuse
    if ((tid & 31) == 0) red[tid >> 5] = s;
    __syncthreads();
    s = 0.f;
#pragma unroll
    for (int w = 0; w < 8; w++) s += red[w];

    const float inv = 1.0f / s;
    for (int i = tid; i < L; i += 256) p[i] *= inv;
}

// ---------------------------------------------------------------------------
// Epilogue: out = gamma*pav + beta*cav + 2*x   (vectorized float4)
// ---------------------------------------------------------------------------
__global__ void epilogue_kernel(const float* __restrict__ x,
                                const float* __restrict__ pav,
                                const float* __restrict__ cav,
                                const float* __restrict__ gamma,
                                const float* __restrict__ beta,
                                float* __restrict__ out, long n4)
{
    long i = (long)blockIdx.x * blockDim.x + threadIdx.x;
    if (i >= n4) return;
    const float g = __ldg(gamma);
    const float bt = __ldg(beta);
    float4 xp = reinterpret_cast<const float4*>(x)[i];
    float4 pp = reinterpret_cast<const float4*>(pav)[i];
    float4 cp = reinterpret_cast<const float4*>(cav)[i];
    float4 o;
    o.x = g * pp.x + bt * cp.x + 2.f * xp.x;
    o.y = g * pp.y + bt * cp.y + 2.f * xp.y;
    o.z = g * pp.z + bt * cp.z + 2.f * xp.z;
    o.w = g * pp.w + bt * cp.w + 2.f * xp.w;
    reinterpret_cast<float4*>(out)[i] = o;
}

// ---------------------------------------------------------------------------
// kernel_launch
// ---------------------------------------------------------------------------
extern "C" void kernel_launch(void* const* d_in, const int* in_sizes, int n_in,
                              void* d_out, int out_size)
{
    const float* x     = (const float*)d_in[0];  // [16,32,32,1280] == [B,N,C]
    const float* Wk    = (const float*)d_in[1];  // [1280,160]
    const float* Wq    = (const float*)d_in[2];  // [1280,160]
    const float* Wv    = (const float*)d_in[3];  // [1280,1280]
    const float* gamma = (const float*)d_in[4];  // [1]
    const float* beta  = (const float*)d_in[5];  // [1]
    float* out = (float*)d_out;

    float *k_, *q_, *v_, *s_, *s2_, *pav_;
    cudaGetSymbolAddress((void**)&k_,   g_k);
    cudaGetSymbolAddress((void**)&q_,   g_q);
    cudaGetSymbolAddress((void**)&v_,   g_v);
    cudaGetSymbolAddress((void**)&s_,   g_s);
    cudaGetSymbolAddress((void**)&s2_,  g_s2);
    cudaGetSymbolAddress((void**)&pav_, g_pav);
    float* cav_ = v_;   // reuse: v dead after pav GEMM

    const dim3 blk(256);

    // k = xf @ Wk   [16384,160] = [16384,1280] @ [1280,160]
    sgemm_kernel<false, false><<<dim3(2, 128, 1), blk>>>(
        x, Wk, k_, SZ_BN, SZ_D, SZ_C, SZ_C, SZ_D, SZ_D, 0, 0, 0);
    // q = xf @ Wq
    sgemm_kernel<false, false><<<dim3(2, 128, 1), blk>>>(
        x, Wq, q_, SZ_BN, SZ_D, SZ_C, SZ_C, SZ_D, SZ_D, 0, 0, 0);
    // v = xf @ Wv   [16384,1280]
    sgemm_kernel<false, false><<<dim3(10, 128, 1), blk>>>(
        x, Wv, v_, SZ_BN, SZ_C, SZ_C, SZ_C, SZ_C, SZ_C, 0, 0, 0);

    // s[b,n,m] = sum_d k[b,n,d] * q[b,m,d]   (NT, batched over 16)
    sgemm_kernel<false, true><<<dim3(8, 8, SZ_B), blk>>>(
        k_, q_, s_, SZ_N, SZ_N, SZ_D, SZ_D, SZ_D, SZ_N,
        (long)SZ_N * SZ_D, (long)SZ_N * SZ_D, (long)SZ_N * SZ_N);

    // p = softmax(s, axis=-1): 16*1024 rows of 1024
    softmax_rows<<<SZ_B * SZ_N, 256>>>(s_, SZ_N);

    // pav[b,n,c] = p[b] @ v[b]   (NN, batched)
    sgemm_kernel<false, false><<<dim3(10, 8, SZ_B), blk>>>(
        s_, v_, pav_, SZ_N, SZ_C, SZ_N, SZ_N, SZ_C, SZ_C,
        (long)SZ_N * SZ_N, (long)SZ_N * SZ_C, (long)SZ_N * SZ_C);

    // s2[b,c,e] = sum_n x[b,n,c] * x[b,n,e]   (TN, batched)
    sgemm_kernel<true, false><<<dim3(10, 10, SZ_B), blk>>>(
        x, x, s2_, SZ_C, SZ_C, SZ_N, SZ_C, SZ_C, SZ_C,
        (long)SZ_N * SZ_C, (long)SZ_N * SZ_C, (long)SZ_C * SZ_C);

    // p2 = softmax(s2, axis=-1): 16*1280 rows of 1280
    softmax_rows<<<SZ_B * SZ_C, 256>>>(s2_, SZ_C);

    // cav[b,n,e] = x[b] @ p2[b]   (NN, batched; writes into g_v, v is dead)
    sgemm_kernel<false, false><<<dim3(10, 8, SZ_B), blk>>>(
        x, s2_, cav_, SZ_N, SZ_C, SZ_C, SZ_C, SZ_C, SZ_C,
        (long)SZ_N * SZ_C, (long)SZ_C * SZ_C, (long)SZ_N * SZ_C);

    // out = gamma*pav + beta*cav + 2*x
    const long n4 = (long)SZ_BN * SZ_C / 4;  // 5,242,880 float4s
    epilogue_kernel<<<(unsigned)((n4 + 255) / 256), 256>>>(
        x, pav_, cav_, gamma, beta, out, n4);
}